// round 14
// baseline (speedup 1.0000x reference)
#include <cuda_runtime.h>
#include <cuda_fp16.h>

typedef unsigned long long ull;

#define NMAX 100000
#define EMAX 3200000
#define NBLK ((NMAX + 1023) / 1024)

// ---------------- device scratch (zero-initialized at load) ----------------
// Feature layout: lane-slot l holds features (l, l+32).
__device__ float2  g_h [(size_t)NMAX * 32];
__device__ __half2 g_hh[(size_t)NMAX * 32];
__device__ int     g_cnt[NMAX];
__device__ int     g_off[NMAX];
__device__ int     g_cur[NMAX];
__device__ int     g_edst[EMAX];
__device__ int     g_part[NBLK + 1];

// ---------------- packed fp32x2 helpers ----------------
__device__ __forceinline__ ull fma2(ull a, ull b, ull c) {
    ull d;
    asm("fma.rn.f32x2 %0, %1, %2, %3;" : "=l"(d) : "l"(a), "l"(b), "l"(c));
    return d;
}
__device__ __forceinline__ float2 unpack2(ull v) {
    unsigned lo, hi;
    asm("mov.b64 {%0,%1}, %2;" : "=r"(lo), "=r"(hi) : "l"(v));
    return make_float2(__uint_as_float(lo), __uint_as_float(hi));
}

__device__ __forceinline__ int detect64(const int* __restrict__ a) {
    int any = 0;
    #pragma unroll
    for (int i = 1; i < 32; i += 2) any |= a[i];
    return any == 0;
}

// k-major quads: quad[q*32+l] = (W[2q][l], W[2q+1][l], W[2q][l+32], W[2q+1][l+32])
__device__ __forceinline__ void build_quads64(float4* dst, const float* __restrict__ W, int tid) {
    for (int i = tid; i < 1024; i += 256) {
        int q = i >> 5, l = i & 31;
        float4 f;
        f.x = W[(2 * q) * 64 + l];
        f.y = W[(2 * q + 1) * 64 + l];
        f.z = W[(2 * q) * 64 + l + 32];
        f.w = W[(2 * q + 1) * 64 + l + 32];
        dst[i] = f;
    }
}

// 8-node k-major GEMV: weight LDS.128 amortized over 8 nodes.
__device__ __forceinline__ void gemv8k(
    const ulonglong2* __restrict__ Wq, const float* a, int lane, float2* o)
{
    ull cl[8] = {0,0,0,0,0,0,0,0};
    ull ch[8] = {0,0,0,0,0,0,0,0};
    #pragma unroll
    for (int q = 0; q < 32; ++q) {
        ulonglong2 w = Wq[q * 32 + lane];
        #pragma unroll
        for (int m = 0; m < 8; ++m) {
            ull v = *(const ull*)(a + m * 64 + 2 * q);
            cl[m] = fma2(w.x, v, cl[m]);
            ch[m] = fma2(w.y, v, ch[m]);
        }
    }
    #pragma unroll
    for (int m = 0; m < 8; ++m) {
        float2 t = unpack2(cl[m]);
        float2 u = unpack2(ch[m]);
        o[m].x = t.x + t.y;
        o[m].y = u.x + u.y;
    }
}

// ============ kernel 1: encoder MLP (8 nodes/warp) + edge degree count ============
__global__ __launch_bounds__(256) void k_enc_count(
    const float* __restrict__ x,
    const float* __restrict__ W1, const float* __restrict__ b1,
    const float* __restrict__ W2, const float* __restrict__ b2,
    const void* __restrict__ adj, int n, int e)
{
    __shared__ float4 sW1q[3 * 32];
    __shared__ float4 sW2q[1024];
    __shared__ float  sx[8][8][8];
    __shared__ float  sact[8][8][64];

    int tid = threadIdx.x;
    for (int i = tid; i < 3 * 32; i += 256) {
        int q = i >> 5, l = i & 31;
        float4 f;
        f.x = W1[(2 * q) * 64 + l];
        f.y = W1[(2 * q + 1) * 64 + l];
        f.z = W1[(2 * q) * 64 + l + 32];
        f.w = W1[(2 * q + 1) * 64 + l + 32];
        sW1q[i] = f;
    }
    build_quads64(sW2q, W2, tid);
    __syncthreads();

    int lane = tid & 31, wp = tid >> 5;
    float b1l = b1[lane], b1h = b1[lane + 32];
    float b2l = b2[lane], b2h = b2[lane + 32];

    int wg = blockIdx.x * 8 + wp, nw = gridDim.x * 8;

    for (int i0 = wg * 8; i0 < n; i0 += nw * 8) {
        #pragma unroll
        for (int idx = lane; idx < 64; idx += 32) {
            int mm = idx >> 3, f = idx & 7;
            int node = min(i0 + mm, n - 1);
            sx[wp][mm][f] = (f < 6) ? x[(size_t)node * 6 + f] : 0.f;
        }
        __syncwarp();

        // GEMV1: 6 -> 64 for 8 nodes
        {
            ull cl[8] = {0,0,0,0,0,0,0,0};
            ull ch[8] = {0,0,0,0,0,0,0,0};
            #pragma unroll
            for (int q = 0; q < 3; ++q) {
                ulonglong2 w = ((const ulonglong2*)sW1q)[q * 32 + lane];
                #pragma unroll
                for (int m = 0; m < 8; ++m) {
                    ull v = *(const ull*)(&sx[wp][m][2 * q]);
                    cl[m] = fma2(w.x, v, cl[m]);
                    ch[m] = fma2(w.y, v, ch[m]);
                }
            }
            #pragma unroll
            for (int m = 0; m < 8; ++m) {
                float2 t = unpack2(cl[m]);
                float2 u = unpack2(ch[m]);
                sact[wp][m][lane]      = fmaxf(t.x + t.y + b1l, 0.f);
                sact[wp][m][lane + 32] = fmaxf(u.x + u.y + b1h, 0.f);
            }
        }
        __syncwarp();

        // GEMV2: 64 -> 64 for 8 nodes
        float2 o[8];
        gemv8k((const ulonglong2*)sW2q, &sact[wp][0][0], lane, o);

        #pragma unroll
        for (int m = 0; m < 8; ++m) {
            int i = i0 + m;
            if (i < n) {
                float2 v = make_float2(o[m].x + b2l, o[m].y + b2h);
                g_h [(size_t)i * 32 + lane] = v;
                g_hh[(size_t)i * 32 + lane] = __float22half2_rn(v);
            }
        }
        __syncwarp();
    }

    // ---- edge degree counts ----
    int is64 = detect64((const int*)adj);
    long long t = blockIdx.x * (long long)blockDim.x + threadIdx.x;
    long long stride = gridDim.x * (long long)blockDim.x;
    int eighth = e >> 3;
    if (is64) {
        const longlong2* ps = (const longlong2*)adj;
        for (long long i = t; i < eighth; i += stride) {
            longlong2 v0 = ps[4 * i];
            longlong2 v1 = ps[4 * i + 1];
            longlong2 v2 = ps[4 * i + 2];
            longlong2 v3 = ps[4 * i + 3];
            atomicAdd(&g_cnt[(int)v0.x], 1); atomicAdd(&g_cnt[(int)v0.y], 1);
            atomicAdd(&g_cnt[(int)v1.x], 1); atomicAdd(&g_cnt[(int)v1.y], 1);
            atomicAdd(&g_cnt[(int)v2.x], 1); atomicAdd(&g_cnt[(int)v2.y], 1);
            atomicAdd(&g_cnt[(int)v3.x], 1); atomicAdd(&g_cnt[(int)v3.y], 1);
        }
        if (t == 0)
            for (int i = eighth << 3; i < e; ++i)
                atomicAdd(&g_cnt[(int)((const long long*)adj)[i]], 1);
    } else {
        const int4* p = (const int4*)adj;
        for (long long i = t; i < eighth; i += stride) {
            int4 v0 = p[2 * i];
            int4 v1 = p[2 * i + 1];
            atomicAdd(&g_cnt[v0.x], 1); atomicAdd(&g_cnt[v0.y], 1);
            atomicAdd(&g_cnt[v0.z], 1); atomicAdd(&g_cnt[v0.w], 1);
            atomicAdd(&g_cnt[v1.x], 1); atomicAdd(&g_cnt[v1.y], 1);
            atomicAdd(&g_cnt[v1.z], 1); atomicAdd(&g_cnt[v1.w], 1);
        }
        if (t == 0)
            for (int i = eighth << 3; i < e; ++i)
                atomicAdd(&g_cnt[((const int*)adj)[i]], 1);
    }
}

// ============ kernel 2a: per-block partial sums ============
__global__ __launch_bounds__(256) void k_partial(int n) {
    __shared__ int sred[256];
    int b = blockIdx.x, tid = threadIdx.x;
    int base = b * 1024;
    int tot = 0;
    #pragma unroll
    for (int j = 0; j < 4; ++j) {
        int i = base + tid + j * 256;
        if (i < n) tot += g_cnt[i];
    }
    sred[tid] = tot;
    __syncthreads();
    for (int d = 128; d > 0; d >>= 1) {
        if (tid < d) sred[tid] += sred[tid + d];
        __syncthreads();
    }
    if (tid == 0) g_part[b] = sred[0];
}

// ============ kernel 2b: per-block scan + write off/cur + zero cnt ============
__global__ __launch_bounds__(256) void k_apply(int n, int nb) {
    __shared__ int sbase[256];
    __shared__ int sscan[512];
    int b = blockIdx.x, tid = threadIdx.x;

    sbase[tid] = (tid < b && tid < nb) ? g_part[tid] : 0;
    __syncthreads();
    for (int d = 128; d > 0; d >>= 1) {
        if (tid < d) sbase[tid] += sbase[tid + d];
        __syncthreads();
    }
    int base = sbase[0];

    int gbase = b * 1024 + tid * 4;
    int c0 = 0, c1 = 0, c2 = 0, c3 = 0;
    if (gbase + 0 < n) c0 = g_cnt[gbase + 0];
    if (gbase + 1 < n) c1 = g_cnt[gbase + 1];
    if (gbase + 2 < n) c2 = g_cnt[gbase + 2];
    if (gbase + 3 < n) c3 = g_cnt[gbase + 3];
    int tsum = c0 + c1 + c2 + c3;

    int pin = 0, pout = 256;
    sscan[pout + tid] = tsum;
    __syncthreads();
    for (int d = 1; d < 256; d <<= 1) {
        int tmp = pin; pin = pout; pout = tmp;
        int v = sscan[pin + tid];
        if (tid >= d) v += sscan[pin + tid - d];
        sscan[pout + tid] = v;
        __syncthreads();
    }
    int incl = sscan[pout + tid];
    int run = base + incl - tsum;

    if (gbase + 0 < n) { g_off[gbase + 0] = run; g_cur[gbase + 0] = run; g_cnt[gbase + 0] = 0; run += c0; }
    if (gbase + 1 < n) { g_off[gbase + 1] = run; g_cur[gbase + 1] = run; g_cnt[gbase + 1] = 0; run += c1; }
    if (gbase + 2 < n) { g_off[gbase + 2] = run; g_cur[gbase + 2] = run; g_cnt[gbase + 2] = 0; run += c2; }
    if (gbase + 3 < n) { g_off[gbase + 3] = run; g_cur[gbase + 3] = run; g_cnt[gbase + 3] = 0; run += c3; }
}

// ============ kernel 3: fill CSR adjacency (8 edges/iter, batched atomics) ============
__global__ void k_fill(const void* __restrict__ adj, int e) {
    int is64 = detect64((const int*)adj);
    long long tid = blockIdx.x * (long long)blockDim.x + threadIdx.x;
    long long stride = gridDim.x * (long long)blockDim.x;
    int eighth = e >> 3;
    if (is64) {
        const long long* a = (const long long*)adj;
        const longlong2* ps = (const longlong2*)a;
        int s[8], d[8], p[8];
        for (long long i = tid; i < eighth; i += stride) {
            #pragma unroll
            for (int j = 0; j < 4; ++j) {
                longlong2 v = ps[4 * i + j];
                s[2 * j] = (int)v.x; s[2 * j + 1] = (int)v.y;
            }
            #pragma unroll
            for (int j = 0; j < 8; ++j) d[j] = (int)a[e + 8 * i + j];
            #pragma unroll
            for (int j = 0; j < 8; ++j) p[j] = atomicAdd(&g_cur[s[j]], 1);
            #pragma unroll
            for (int j = 0; j < 8; ++j) g_edst[p[j]] = d[j];
        }
        if (tid == 0)
            for (int i = eighth << 3; i < e; ++i) {
                int pp = atomicAdd(&g_cur[(int)a[i]], 1);
                g_edst[pp] = (int)a[e + i];
            }
    } else {
        const int* a = (const int*)adj;
        const int4* ps = (const int4*)a;
        int s[8], d[8], p[8];
        for (long long i = tid; i < eighth; i += stride) {
            int4 v0 = ps[2 * i], v1 = ps[2 * i + 1];
            s[0] = v0.x; s[1] = v0.y; s[2] = v0.z; s[3] = v0.w;
            s[4] = v1.x; s[5] = v1.y; s[6] = v1.z; s[7] = v1.w;
            #pragma unroll
            for (int j = 0; j < 8; ++j) d[j] = a[e + 8 * i + j];
            #pragma unroll
            for (int j = 0; j < 8; ++j) p[j] = atomicAdd(&g_cur[s[j]], 1);
            #pragma unroll
            for (int j = 0; j < 8; ++j) g_edst[p[j]] = d[j];
        }
        if (tid == 0)
            for (int i = eighth << 3; i < e; ++i) {
                int pp = atomicAdd(&g_cur[a[i]], 1);
                g_edst[pp] = a[e + i];
            }
    }
}

// ============ kernel 4: gather (scatter-mean), warp per node, 8-deep MLP ============
__global__ __launch_bounds__(256) void k_gather(int n) {
    int lane = threadIdx.x & 31, wp = threadIdx.x >> 5;
    int wg = blockIdx.x * 8 + wp, nw = gridDim.x * 8;
    const __half2* hh = g_hh;

    for (int i = wg; i < n; i += nw) {
        int start = g_off[i];
        int deg = g_cur[i] - start;
        __half2 z = __float2half2_rn(0.f);
        __half2 s0 = z, s1 = z, s2 = z, s3 = z;

        for (int base = 0; base < deg; base += 32) {
            int e = base + lane;
            int d = (e < deg) ? g_edst[start + e] : 0;
            int cnt = min(32, deg - base);
            int j = 0;
            for (; j + 8 <= cnt; j += 8) {
                int d0 = __shfl_sync(0xffffffffu, d, j);
                int d1 = __shfl_sync(0xffffffffu, d, j + 1);
                int d2 = __shfl_sync(0xffffffffu, d, j + 2);
                int d3 = __shfl_sync(0xffffffffu, d, j + 3);
                int d4 = __shfl_sync(0xffffffffu, d, j + 4);
                int d5 = __shfl_sync(0xffffffffu, d, j + 5);
                int d6 = __shfl_sync(0xffffffffu, d, j + 6);
                int d7 = __shfl_sync(0xffffffffu, d, j + 7);
                __half2 v0 = hh[(size_t)d0 * 32 + lane];
                __half2 v1 = hh[(size_t)d1 * 32 + lane];
                __half2 v2 = hh[(size_t)d2 * 32 + lane];
                __half2 v3 = hh[(size_t)d3 * 32 + lane];
                __half2 v4 = hh[(size_t)d4 * 32 + lane];
                __half2 v5 = hh[(size_t)d5 * 32 + lane];
                __half2 v6 = hh[(size_t)d6 * 32 + lane];
                __half2 v7 = hh[(size_t)d7 * 32 + lane];
                s0 = __hadd2(s0, v0); s1 = __hadd2(s1, v1);
                s2 = __hadd2(s2, v2); s3 = __hadd2(s3, v3);
                s0 = __hadd2(s0, v4); s1 = __hadd2(s1, v5);
                s2 = __hadd2(s2, v6); s3 = __hadd2(s3, v7);
            }
            for (; j + 4 <= cnt; j += 4) {
                int d0 = __shfl_sync(0xffffffffu, d, j);
                int d1 = __shfl_sync(0xffffffffu, d, j + 1);
                int d2 = __shfl_sync(0xffffffffu, d, j + 2);
                int d3 = __shfl_sync(0xffffffffu, d, j + 3);
                s0 = __hadd2(s0, hh[(size_t)d0 * 32 + lane]);
                s1 = __hadd2(s1, hh[(size_t)d1 * 32 + lane]);
                s2 = __hadd2(s2, hh[(size_t)d2 * 32 + lane]);
                s3 = __hadd2(s3, hh[(size_t)d3 * 32 + lane]);
            }
            for (; j < cnt; ++j) {
                int dd = __shfl_sync(0xffffffffu, d, j);
                s0 = __hadd2(s0, hh[(size_t)dd * 32 + lane]);
            }
        }
        float2 f0 = __half22float2(s0), f1 = __half22float2(s1);
        float2 f2 = __half22float2(s2), f3 = __half22float2(s3);
        float2 sum = make_float2((f0.x + f1.x) + (f2.x + f3.x),
                                 (f0.y + f1.y) + (f2.y + f3.y));
        float inv = 1.f / fmaxf((float)deg, 1.f);
        float2 self = g_h[(size_t)i * 32 + lane];
        g_h[(size_t)i * 32 + lane] =
            make_float2(fmaf(sum.x, inv, self.x), fmaf(sum.y, inv, self.y));
    }
}

// ============ kernel 5: MLP chain Wf1+Wf2+heads (8 nodes/warp) ============
#define FQ_WF1 0
#define FQ_WF2 1024
#define FQ_WH  2048
#define FQ_ACT 3072
static const int MLP_SMEM = 3072 * 16 + 16384;   // 65536 B

__global__ __launch_bounds__(256, 3) void k_mlp(
    const float* __restrict__ bf1, const float* __restrict__ bf2,
    const float* __restrict__ Wf1, const float* __restrict__ Wf2,
    const float* __restrict__ Ws1, const float* __restrict__ bs1,
    const float* __restrict__ Ws2, const float* __restrict__ bs2,
    const float* __restrict__ Wt1, const float* __restrict__ bt1,
    const float* __restrict__ Wt2, const float* __restrict__ bt2,
    float* __restrict__ out, int n)
{
    extern __shared__ float4 smem4[];
    float4* sWf1 = smem4 + FQ_WF1;
    float4* sWf2 = smem4 + FQ_WF2;
    float4* sWh  = smem4 + FQ_WH;
    float*  sactbase = (float*)(smem4 + FQ_ACT);

    int tid = threadIdx.x;
    build_quads64(sWf1, Wf1, tid);
    build_quads64(sWf2, Wf2, tid);
    for (int i = tid; i < 1024; i += 256) {
        int q = i >> 5, l = i & 31;
        float4 f;
        f.x = Ws1[(2 * q) * 32 + l];
        f.y = Ws1[(2 * q + 1) * 32 + l];
        f.z = Wt1[(2 * q) * 32 + l];
        f.w = Wt1[(2 * q + 1) * 32 + l];
        sWh[i] = f;
    }
    __syncthreads();

    int lane = tid & 31, wp = tid >> 5;
    float* acts = sactbase + wp * 512;

    float bf1l = bf1[lane], bf1h = bf1[lane + 32];
    float bf2l = bf2[lane], bf2h = bf2[lane + 32];
    float bs1v = bs1[lane], bt1v = bt1[lane];
    float ws2v = Ws2[lane];
    float4 wt2v = ((const float4*)Wt2)[lane];
    float bs2v = bs2[0];
    float4 bt2v = ((const float4*)bt2)[0];

    int wg = blockIdx.x * 8 + wp, nw = gridDim.x * 8;
    float4* tout = (float4*)(out + n);

    for (int i0 = wg * 8; i0 < n; i0 += nw * 8) {
        #pragma unroll
        for (int m = 0; m < 8; ++m) {
            int i = min(i0 + m, n - 1);
            float2 v = g_h[(size_t)i * 32 + lane];
            float* am = acts + m * 64;
            am[lane]      = v.x;
            am[lane + 32] = v.y;
        }
        __syncwarp();

        // GEMV 1
        float2 o[8];
        gemv8k((const ulonglong2*)sWf1, acts, lane, o);
        __syncwarp();
        #pragma unroll
        for (int m = 0; m < 8; ++m) {
            float* am = acts + m * 64;
            am[lane]      = fmaxf(o[m].x + bf1l, 0.f);
            am[lane + 32] = fmaxf(o[m].y + bf1h, 0.f);
        }
        __syncwarp();

        // GEMV 2
        gemv8k((const ulonglong2*)sWf2, acts, lane, o);
        __syncwarp();
        #pragma unroll
        for (int m = 0; m < 8; ++m) {
            float* am = acts + m * 64;
            am[lane]      = fmaxf(o[m].x + bf2l, 0.f);
            am[lane + 32] = fmaxf(o[m].y + bf2h, 0.f);
        }
        __syncwarp();

        // GEMV 3 heads
        gemv8k((const ulonglong2*)sWh, acts, lane, o);

        #pragma unroll
        for (int m = 0; m < 8; ++m) {
            float us = fmaxf(o[m].x + bs1v, 0.f);
            float ut = fmaxf(o[m].y + bt1v, 0.f);
            float p  = us * ws2v;
            float tx = ut * wt2v.x, ty = ut * wt2v.y, tz = ut * wt2v.z, tw = ut * wt2v.w;
            #pragma unroll
            for (int s = 16; s; s >>= 1) {
                p  += __shfl_xor_sync(0xffffffffu, p,  s);
                tx += __shfl_xor_sync(0xffffffffu, tx, s);
                ty += __shfl_xor_sync(0xffffffffu, ty, s);
                tz += __shfl_xor_sync(0xffffffffu, tz, s);
                tw += __shfl_xor_sync(0xffffffffu, tw, s);
            }
            int i = i0 + m;
            if (lane == 0 && i < n) {
                out[i] = p + bs2v;
                tout[i] = make_float4(tx + bt2v.x, ty + bt2v.y, tz + bt2v.z, tw + bt2v.w);
            }
        }
        __syncwarp();
    }
}

// ---------------- launch ----------------
extern "C" void kernel_launch(void* const* d_in, const int* in_sizes, int n_in,
                              void* d_out, int out_size) {
    const float* x   = (const float*)d_in[0];
    const void*  adj = d_in[1];
    const float* W1  = (const float*)d_in[2];
    const float* b1  = (const float*)d_in[3];
    const float* W2  = (const float*)d_in[4];
    const float* b2  = (const float*)d_in[5];
    const float* Wf1 = (const float*)d_in[6];
    const float* bf1 = (const float*)d_in[7];
    const float* Wf2 = (const float*)d_in[8];
    const float* bf2 = (const float*)d_in[9];
    const float* Ws1 = (const float*)d_in[10];
    const float* bs1 = (const float*)d_in[11];
    const float* Ws2 = (const float*)d_in[12];
    const float* bs2 = (const float*)d_in[13];
    const float* Wt1 = (const float*)d_in[14];
    const float* bt1 = (const float*)d_in[15];
    const float* Wt2 = (const float*)d_in[16];
    const float* bt2 = (const float*)d_in[17];

    int n = in_sizes[0] / 6;
    int e = in_sizes[1] / 2;
    float* out = (float*)d_out;
    int nb = (n + 1023) / 1024;

    cudaFuncSetAttribute(k_mlp, cudaFuncAttributeMaxDynamicSharedMemorySize, MLP_SMEM);

    // balanced grids: 12500 8-node groups
    //  enc: 782 blocks * 8 warps -> exactly 2 groups/warp
    //  mlp: 391 blocks * 8 warps -> ~4 groups/warp, single wave (<=444 at 3 CTA/SM)
    //  gather: 1184 blocks = one full wave at 8 CTA/SM
    k_enc_count<<<782, 256>>>(x, W1, b1, W2, b2, adj, n, e);
    k_partial<<<nb, 256>>>(n);
    k_apply<<<nb, 256>>>(n, nb);
    k_fill<<<2048, 256>>>(adj, e);
    k_gather<<<1184, 256>>>(n);
    k_mlp<<<391, 256, MLP_SMEM>>>(bf1, bf2, Wf1, Wf2, Ws1, bs1, Ws2, bs2,
                                  Wt1, bt1, Wt2, bt2, out, n);
}

// round 15
// speedup vs baseline: 1.0793x; 1.0793x over previous
#include <cuda_runtime.h>
#include <cuda_fp16.h>

typedef unsigned long long ull;

#define NMAX 100000
#define EMAX 3200000
#define NBLK ((NMAX + 1023) / 1024)

// ---------------- device scratch (zero-initialized at load) ----------------
// Feature layout: lane-slot l holds features (l, l+32).
__device__ float2  g_h [(size_t)NMAX * 32];
__device__ __half2 g_hh[(size_t)NMAX * 32];
__device__ int     g_cnt[NMAX];
__device__ int     g_off[NMAX];
__device__ int     g_cur[NMAX];
__device__ int     g_edst[EMAX];
__device__ int     g_part[NBLK + 1];

// ---------------- packed fp32x2 helpers ----------------
__device__ __forceinline__ ull fma2(ull a, ull b, ull c) {
    ull d;
    asm("fma.rn.f32x2 %0, %1, %2, %3;" : "=l"(d) : "l"(a), "l"(b), "l"(c));
    return d;
}
__device__ __forceinline__ float2 unpack2(ull v) {
    unsigned lo, hi;
    asm("mov.b64 {%0,%1}, %2;" : "=r"(lo), "=r"(hi) : "l"(v));
    return make_float2(__uint_as_float(lo), __uint_as_float(hi));
}

__device__ __forceinline__ int detect64(const int* __restrict__ a) {
    int any = 0;
    #pragma unroll
    for (int i = 1; i < 32; i += 2) any |= a[i];
    return any == 0;
}

// k-major quads: quad[q*32+l] = (W[2q][l], W[2q+1][l], W[2q][l+32], W[2q+1][l+32])
__device__ __forceinline__ void build_quads64(float4* dst, const float* __restrict__ W, int tid) {
    for (int i = tid; i < 1024; i += 256) {
        int q = i >> 5, l = i & 31;
        float4 f;
        f.x = W[(2 * q) * 64 + l];
        f.y = W[(2 * q + 1) * 64 + l];
        f.z = W[(2 * q) * 64 + l + 32];
        f.w = W[(2 * q + 1) * 64 + l + 32];
        dst[i] = f;
    }
}

// 8-node k-major GEMV: weight LDS.128 amortized over 8 nodes.
__device__ __forceinline__ void gemv8k(
    const ulonglong2* __restrict__ Wq, const float* a, int lane, float2* o)
{
    ull cl[8] = {0,0,0,0,0,0,0,0};
    ull ch[8] = {0,0,0,0,0,0,0,0};
    #pragma unroll
    for (int q = 0; q < 32; ++q) {
        ulonglong2 w = Wq[q * 32 + lane];
        #pragma unroll
        for (int m = 0; m < 8; ++m) {
            ull v = *(const ull*)(a + m * 64 + 2 * q);
            cl[m] = fma2(w.x, v, cl[m]);
            ch[m] = fma2(w.y, v, ch[m]);
        }
    }
    #pragma unroll
    for (int m = 0; m < 8; ++m) {
        float2 t = unpack2(cl[m]);
        float2 u = unpack2(ch[m]);
        o[m].x = t.x + t.y;
        o[m].y = u.x + u.y;
    }
}

// ============ kernel 1: encoder MLP (8 nodes/warp) + edge degree count ============
__global__ __launch_bounds__(256) void k_enc_count(
    const float* __restrict__ x,
    const float* __restrict__ W1, const float* __restrict__ b1,
    const float* __restrict__ W2, const float* __restrict__ b2,
    const void* __restrict__ adj, int n, int e)
{
    __shared__ float4 sW1q[3 * 32];
    __shared__ float4 sW2q[1024];
    __shared__ float  sx[8][8][8];
    __shared__ float  sact[8][8][64];

    int tid = threadIdx.x;
    for (int i = tid; i < 3 * 32; i += 256) {
        int q = i >> 5, l = i & 31;
        float4 f;
        f.x = W1[(2 * q) * 64 + l];
        f.y = W1[(2 * q + 1) * 64 + l];
        f.z = W1[(2 * q) * 64 + l + 32];
        f.w = W1[(2 * q + 1) * 64 + l + 32];
        sW1q[i] = f;
    }
    build_quads64(sW2q, W2, tid);
    __syncthreads();

    int lane = tid & 31, wp = tid >> 5;
    float b1l = b1[lane], b1h = b1[lane + 32];
    float b2l = b2[lane], b2h = b2[lane + 32];

    int wg = blockIdx.x * 8 + wp, nw = gridDim.x * 8;

    for (int i0 = wg * 8; i0 < n; i0 += nw * 8) {
        #pragma unroll
        for (int idx = lane; idx < 64; idx += 32) {
            int mm = idx >> 3, f = idx & 7;
            int node = min(i0 + mm, n - 1);
            sx[wp][mm][f] = (f < 6) ? x[(size_t)node * 6 + f] : 0.f;
        }
        __syncwarp();

        // GEMV1: 6 -> 64 for 8 nodes
        {
            ull cl[8] = {0,0,0,0,0,0,0,0};
            ull ch[8] = {0,0,0,0,0,0,0,0};
            #pragma unroll
            for (int q = 0; q < 3; ++q) {
                ulonglong2 w = ((const ulonglong2*)sW1q)[q * 32 + lane];
                #pragma unroll
                for (int m = 0; m < 8; ++m) {
                    ull v = *(const ull*)(&sx[wp][m][2 * q]);
                    cl[m] = fma2(w.x, v, cl[m]);
                    ch[m] = fma2(w.y, v, ch[m]);
                }
            }
            #pragma unroll
            for (int m = 0; m < 8; ++m) {
                float2 t = unpack2(cl[m]);
                float2 u = unpack2(ch[m]);
                sact[wp][m][lane]      = fmaxf(t.x + t.y + b1l, 0.f);
                sact[wp][m][lane + 32] = fmaxf(u.x + u.y + b1h, 0.f);
            }
        }
        __syncwarp();

        // GEMV2: 64 -> 64 for 8 nodes
        float2 o[8];
        gemv8k((const ulonglong2*)sW2q, &sact[wp][0][0], lane, o);

        #pragma unroll
        for (int m = 0; m < 8; ++m) {
            int i = i0 + m;
            if (i < n) {
                float2 v = make_float2(o[m].x + b2l, o[m].y + b2h);
                g_h [(size_t)i * 32 + lane] = v;
                g_hh[(size_t)i * 32 + lane] = __float22half2_rn(v);
            }
        }
        __syncwarp();
    }

    // ---- edge degree counts (overlaps other blocks' MLP work) ----
    int is64 = detect64((const int*)adj);
    long long t = blockIdx.x * (long long)blockDim.x + threadIdx.x;
    long long stride = gridDim.x * (long long)blockDim.x;
    int eighth = e >> 3;
    if (is64) {
        const longlong2* ps = (const longlong2*)adj;
        for (long long i = t; i < eighth; i += stride) {
            longlong2 v0 = ps[4 * i];
            longlong2 v1 = ps[4 * i + 1];
            longlong2 v2 = ps[4 * i + 2];
            longlong2 v3 = ps[4 * i + 3];
            atomicAdd(&g_cnt[(int)v0.x], 1); atomicAdd(&g_cnt[(int)v0.y], 1);
            atomicAdd(&g_cnt[(int)v1.x], 1); atomicAdd(&g_cnt[(int)v1.y], 1);
            atomicAdd(&g_cnt[(int)v2.x], 1); atomicAdd(&g_cnt[(int)v2.y], 1);
            atomicAdd(&g_cnt[(int)v3.x], 1); atomicAdd(&g_cnt[(int)v3.y], 1);
        }
        if (t == 0)
            for (int i = eighth << 3; i < e; ++i)
                atomicAdd(&g_cnt[(int)((const long long*)adj)[i]], 1);
    } else {
        const int4* p = (const int4*)adj;
        for (long long i = t; i < eighth; i += stride) {
            int4 v0 = p[2 * i];
            int4 v1 = p[2 * i + 1];
            atomicAdd(&g_cnt[v0.x], 1); atomicAdd(&g_cnt[v0.y], 1);
            atomicAdd(&g_cnt[v0.z], 1); atomicAdd(&g_cnt[v0.w], 1);
            atomicAdd(&g_cnt[v1.x], 1); atomicAdd(&g_cnt[v1.y], 1);
            atomicAdd(&g_cnt[v1.z], 1); atomicAdd(&g_cnt[v1.w], 1);
        }
        if (t == 0)
            for (int i = eighth << 3; i < e; ++i)
                atomicAdd(&g_cnt[((const int*)adj)[i]], 1);
    }
}

// ============ kernel 2a: per-block partial sums ============
__global__ __launch_bounds__(256) void k_partial(int n) {
    __shared__ int sred[256];
    int b = blockIdx.x, tid = threadIdx.x;
    int base = b * 1024;
    int tot = 0;
    #pragma unroll
    for (int j = 0; j < 4; ++j) {
        int i = base + tid + j * 256;
        if (i < n) tot += g_cnt[i];
    }
    sred[tid] = tot;
    __syncthreads();
    for (int d = 128; d > 0; d >>= 1) {
        if (tid < d) sred[tid] += sred[tid + d];
        __syncthreads();
    }
    if (tid == 0) g_part[b] = sred[0];
}

// ============ kernel 2b: per-block scan + write off/cur + zero cnt ============
__global__ __launch_bounds__(256) void k_apply(int n, int nb) {
    __shared__ int sbase[256];
    __shared__ int sscan[512];
    int b = blockIdx.x, tid = threadIdx.x;

    sbase[tid] = (tid < b && tid < nb) ? g_part[tid] : 0;
    __syncthreads();
    for (int d = 128; d > 0; d >>= 1) {
        if (tid < d) sbase[tid] += sbase[tid + d];
        __syncthreads();
    }
    int base = sbase[0];

    int gbase = b * 1024 + tid * 4;
    int c0 = 0, c1 = 0, c2 = 0, c3 = 0;
    if (gbase + 0 < n) c0 = g_cnt[gbase + 0];
    if (gbase + 1 < n) c1 = g_cnt[gbase + 1];
    if (gbase + 2 < n) c2 = g_cnt[gbase + 2];
    if (gbase + 3 < n) c3 = g_cnt[gbase + 3];
    int tsum = c0 + c1 + c2 + c3;

    int pin = 0, pout = 256;
    sscan[pout + tid] = tsum;
    __syncthreads();
    for (int d = 1; d < 256; d <<= 1) {
        int tmp = pin; pin = pout; pout = tmp;
        int v = sscan[pin + tid];
        if (tid >= d) v += sscan[pin + tid - d];
        sscan[pout + tid] = v;
        __syncthreads();
    }
    int incl = sscan[pout + tid];
    int run = base + incl - tsum;

    if (gbase + 0 < n) { g_off[gbase + 0] = run; g_cur[gbase + 0] = run; g_cnt[gbase + 0] = 0; run += c0; }
    if (gbase + 1 < n) { g_off[gbase + 1] = run; g_cur[gbase + 1] = run; g_cnt[gbase + 1] = 0; run += c1; }
    if (gbase + 2 < n) { g_off[gbase + 2] = run; g_cur[gbase + 2] = run; g_cnt[gbase + 2] = 0; run += c2; }
    if (gbase + 3 < n) { g_off[gbase + 3] = run; g_cur[gbase + 3] = run; g_cnt[gbase + 3] = 0; run += c3; }
}

// ============ kernel 3: fill CSR adjacency (8 edges/iter) ============
__global__ void k_fill(const void* __restrict__ adj, int e) {
    int is64 = detect64((const int*)adj);
    long long tid = blockIdx.x * (long long)blockDim.x + threadIdx.x;
    long long stride = gridDim.x * (long long)blockDim.x;
    int eighth = e >> 3;
    if (is64) {
        const long long* a = (const long long*)adj;
        const longlong2* ps = (const longlong2*)a;
        int s[8], d[8];
        for (long long i = tid; i < eighth; i += stride) {
            #pragma unroll
            for (int j = 0; j < 4; ++j) {
                longlong2 v = ps[4 * i + j];
                s[2 * j] = (int)v.x; s[2 * j + 1] = (int)v.y;
            }
            #pragma unroll
            for (int j = 0; j < 8; ++j) d[j] = (int)a[e + 8 * i + j];
            #pragma unroll
            for (int j = 0; j < 8; ++j) {
                int p = atomicAdd(&g_cur[s[j]], 1);
                g_edst[p] = d[j];
            }
        }
        if (tid == 0)
            for (int i = eighth << 3; i < e; ++i) {
                int p = atomicAdd(&g_cur[(int)a[i]], 1);
                g_edst[p] = (int)a[e + i];
            }
    } else {
        const int* a = (const int*)adj;
        const int4* ps = (const int4*)a;
        int s[8], d[8];
        for (long long i = tid; i < eighth; i += stride) {
            int4 v0 = ps[2 * i], v1 = ps[2 * i + 1];
            s[0] = v0.x; s[1] = v0.y; s[2] = v0.z; s[3] = v0.w;
            s[4] = v1.x; s[5] = v1.y; s[6] = v1.z; s[7] = v1.w;
            #pragma unroll
            for (int j = 0; j < 8; ++j) d[j] = a[e + 8 * i + j];
            #pragma unroll
            for (int j = 0; j < 8; ++j) {
                int p = atomicAdd(&g_cur[s[j]], 1);
                g_edst[p] = d[j];
            }
        }
        if (tid == 0)
            for (int i = eighth << 3; i < e; ++i) {
                int p = atomicAdd(&g_cur[a[i]], 1);
                g_edst[p] = a[e + i];
            }
    }
}

// ============ kernel 4: gather (scatter-mean), warp per node, 8-deep MLP ============
__global__ __launch_bounds__(256) void k_gather(int n) {
    int lane = threadIdx.x & 31, wp = threadIdx.x >> 5;
    int wg = blockIdx.x * 8 + wp, nw = gridDim.x * 8;
    const __half2* hh = g_hh;

    for (int i = wg; i < n; i += nw) {
        int start = g_off[i];
        int deg = g_cur[i] - start;
        __half2 z = __float2half2_rn(0.f);
        __half2 s0 = z, s1 = z, s2 = z, s3 = z;

        for (int base = 0; base < deg; base += 32) {
            int e = base + lane;
            int d = (e < deg) ? g_edst[start + e] : 0;
            int cnt = min(32, deg - base);
            int j = 0;
            for (; j + 8 <= cnt; j += 8) {
                int d0 = __shfl_sync(0xffffffffu, d, j);
                int d1 = __shfl_sync(0xffffffffu, d, j + 1);
                int d2 = __shfl_sync(0xffffffffu, d, j + 2);
                int d3 = __shfl_sync(0xffffffffu, d, j + 3);
                int d4 = __shfl_sync(0xffffffffu, d, j + 4);
                int d5 = __shfl_sync(0xffffffffu, d, j + 5);
                int d6 = __shfl_sync(0xffffffffu, d, j + 6);
                int d7 = __shfl_sync(0xffffffffu, d, j + 7);
                __half2 v0 = hh[(size_t)d0 * 32 + lane];
                __half2 v1 = hh[(size_t)d1 * 32 + lane];
                __half2 v2 = hh[(size_t)d2 * 32 + lane];
                __half2 v3 = hh[(size_t)d3 * 32 + lane];
                __half2 v4 = hh[(size_t)d4 * 32 + lane];
                __half2 v5 = hh[(size_t)d5 * 32 + lane];
                __half2 v6 = hh[(size_t)d6 * 32 + lane];
                __half2 v7 = hh[(size_t)d7 * 32 + lane];
                s0 = __hadd2(s0, v0); s1 = __hadd2(s1, v1);
                s2 = __hadd2(s2, v2); s3 = __hadd2(s3, v3);
                s0 = __hadd2(s0, v4); s1 = __hadd2(s1, v5);
                s2 = __hadd2(s2, v6); s3 = __hadd2(s3, v7);
            }
            for (; j + 4 <= cnt; j += 4) {
                int d0 = __shfl_sync(0xffffffffu, d, j);
                int d1 = __shfl_sync(0xffffffffu, d, j + 1);
                int d2 = __shfl_sync(0xffffffffu, d, j + 2);
                int d3 = __shfl_sync(0xffffffffu, d, j + 3);
                s0 = __hadd2(s0, hh[(size_t)d0 * 32 + lane]);
                s1 = __hadd2(s1, hh[(size_t)d1 * 32 + lane]);
                s2 = __hadd2(s2, hh[(size_t)d2 * 32 + lane]);
                s3 = __hadd2(s3, hh[(size_t)d3 * 32 + lane]);
            }
            for (; j < cnt; ++j) {
                int dd = __shfl_sync(0xffffffffu, d, j);
                s0 = __hadd2(s0, hh[(size_t)dd * 32 + lane]);
            }
        }
        float2 f0 = __half22float2(s0), f1 = __half22float2(s1);
        float2 f2 = __half22float2(s2), f3 = __half22float2(s3);
        float2 sum = make_float2((f0.x + f1.x) + (f2.x + f3.x),
                                 (f0.y + f1.y) + (f2.y + f3.y));
        float inv = 1.f / fmaxf((float)deg, 1.f);
        float2 self = g_h[(size_t)i * 32 + lane];
        g_h[(size_t)i * 32 + lane] =
            make_float2(fmaf(sum.x, inv, self.x), fmaf(sum.y, inv, self.y));
    }
}

// ============ kernel 5: MLP chain Wf1+Wf2+heads (8 nodes/warp) ============
#define FQ_WF1 0
#define FQ_WF2 1024
#define FQ_WH  2048
#define FQ_ACT 3072
static const int MLP_SMEM = 3072 * 16 + 16384;   // 65536 B

__global__ __launch_bounds__(256, 3) void k_mlp(
    const float* __restrict__ bf1, const float* __restrict__ bf2,
    const float* __restrict__ Wf1, const float* __restrict__ Wf2,
    const float* __restrict__ Ws1, const float* __restrict__ bs1,
    const float* __restrict__ Ws2, const float* __restrict__ bs2,
    const float* __restrict__ Wt1, const float* __restrict__ bt1,
    const float* __restrict__ Wt2, const float* __restrict__ bt2,
    float* __restrict__ out, int n)
{
    extern __shared__ float4 smem4[];
    float4* sWf1 = smem4 + FQ_WF1;
    float4* sWf2 = smem4 + FQ_WF2;
    float4* sWh  = smem4 + FQ_WH;
    float*  sactbase = (float*)(smem4 + FQ_ACT);

    int tid = threadIdx.x;
    build_quads64(sWf1, Wf1, tid);
    build_quads64(sWf2, Wf2, tid);
    for (int i = tid; i < 1024; i += 256) {
        int q = i >> 5, l = i & 31;
        float4 f;
        f.x = Ws1[(2 * q) * 32 + l];
        f.y = Ws1[(2 * q + 1) * 32 + l];
        f.z = Wt1[(2 * q) * 32 + l];
        f.w = Wt1[(2 * q + 1) * 32 + l];
        sWh[i] = f;
    }
    __syncthreads();

    int lane = tid & 31, wp = tid >> 5;
    float* acts = sactbase + wp * 512;

    float bf1l = bf1[lane], bf1h = bf1[lane + 32];
    float bf2l = bf2[lane], bf2h = bf2[lane + 32];
    float bs1v = bs1[lane], bt1v = bt1[lane];
    float ws2v = Ws2[lane];
    float4 wt2v = ((const float4*)Wt2)[lane];
    float bs2v = bs2[0];
    float4 bt2v = ((const float4*)bt2)[0];

    int wg = blockIdx.x * 8 + wp, nw = gridDim.x * 8;
    float4* tout = (float4*)(out + n);

    for (int i0 = wg * 8; i0 < n; i0 += nw * 8) {
        #pragma unroll
        for (int m = 0; m < 8; ++m) {
            int i = min(i0 + m, n - 1);
            float2 v = g_h[(size_t)i * 32 + lane];
            float* am = acts + m * 64;
            am[lane]      = v.x;
            am[lane + 32] = v.y;
        }
        __syncwarp();

        // GEMV 1
        float2 o[8];
        gemv8k((const ulonglong2*)sWf1, acts, lane, o);
        __syncwarp();
        #pragma unroll
        for (int m = 0; m < 8; ++m) {
            float* am = acts + m * 64;
            am[lane]      = fmaxf(o[m].x + bf1l, 0.f);
            am[lane + 32] = fmaxf(o[m].y + bf1h, 0.f);
        }
        __syncwarp();

        // GEMV 2
        gemv8k((const ulonglong2*)sWf2, acts, lane, o);
        __syncwarp();
        #pragma unroll
        for (int m = 0; m < 8; ++m) {
            float* am = acts + m * 64;
            am[lane]      = fmaxf(o[m].x + bf2l, 0.f);
            am[lane + 32] = fmaxf(o[m].y + bf2h, 0.f);
        }
        __syncwarp();

        // GEMV 3 heads
        gemv8k((const ulonglong2*)sWh, acts, lane, o);

        #pragma unroll
        for (int m = 0; m < 8; ++m) {
            float us = fmaxf(o[m].x + bs1v, 0.f);
            float ut = fmaxf(o[m].y + bt1v, 0.f);
            float p  = us * ws2v;
            float tx = ut * wt2v.x, ty = ut * wt2v.y, tz = ut * wt2v.z, tw = ut * wt2v.w;
            #pragma unroll
            for (int s = 16; s; s >>= 1) {
                p  += __shfl_xor_sync(0xffffffffu, p,  s);
                tx += __shfl_xor_sync(0xffffffffu, tx, s);
                ty += __shfl_xor_sync(0xffffffffu, ty, s);
                tz += __shfl_xor_sync(0xffffffffu, tz, s);
                tw += __shfl_xor_sync(0xffffffffu, tw, s);
            }
            int i = i0 + m;
            if (lane == 0 && i < n) {
                out[i] = p + bs2v;
                tout[i] = make_float4(tx + bt2v.x, ty + bt2v.y, tz + bt2v.z, tw + bt2v.w);
            }
        }
        __syncwarp();
    }
}

// ---------------- launch ----------------
extern "C" void kernel_launch(void* const* d_in, const int* in_sizes, int n_in,
                              void* d_out, int out_size) {
    const float* x   = (const float*)d_in[0];
    const void*  adj = d_in[1];
    const float* W1  = (const float*)d_in[2];
    const float* b1  = (const float*)d_in[3];
    const float* W2  = (const float*)d_in[4];
    const float* b2  = (const float*)d_in[5];
    const float* Wf1 = (const float*)d_in[6];
    const float* bf1 = (const float*)d_in[7];
    const float* Wf2 = (const float*)d_in[8];
    const float* bf2 = (const float*)d_in[9];
    const float* Ws1 = (const float*)d_in[10];
    const float* bs1 = (const float*)d_in[11];
    const float* Ws2 = (const float*)d_in[12];
    const float* bs2 = (const float*)d_in[13];
    const float* Wt1 = (const float*)d_in[14];
    const float* bt1 = (const float*)d_in[15];
    const float* Wt2 = (const float*)d_in[16];
    const float* bt2 = (const float*)d_in[17];

    int n = in_sizes[0] / 6;
    int e = in_sizes[1] / 2;
    float* out = (float*)d_out;
    int nb = (n + 1023) / 1024;

    cudaFuncSetAttribute(k_mlp, cudaFuncAttributeMaxDynamicSharedMemorySize, MLP_SMEM);

    // round-13 proven configuration: oversubscribed grids for latency-bound
    // kernels (enc_count / fill / gather), single-wave for throughput-bound mlp
    k_enc_count<<<1184, 256>>>(x, W1, b1, W2, b2, adj, n, e);
    k_partial<<<nb, 256>>>(n);
    k_apply<<<nb, 256>>>(n, nb);
    k_fill<<<2048, 256>>>(adj, e);
    k_gather<<<2048, 256>>>(n);
    k_mlp<<<444, 256, MLP_SMEM>>>(bf1, bf2, Wf1, Wf2, Ws1, bs1, Ws2, bs2,
                                  Wt1, bt1, Wt2, bt2, out, n);
}